// round 1
// baseline (speedup 1.0000x reference)
#include <cuda_runtime.h>
#include <cstdint>

#define B_   8
#define N_   4096
#define S_   1024
#define NS_  32
#define CIN  64
#define CMLP 128
#define COUT 256
#define R2_  0.0225f   // 0.15^2

// ---------------- scratch (static device memory, allowed) ----------------
__device__ float g_W[CIN * COUT];          // W1 @ Wc
__device__ float g_bias2[COUT];            // b1 @ Wc + bc
__device__ float g_feats2[(size_t)B_ * N_ * COUT];   // points @ W + bias2
__device__ int   g_fps[B_ * S_];
__device__ int   g_gidx[B_ * S_ * NS_];
__device__ int   g_cnt[B_ * N_];
__device__ float g_sum[COUT];
__device__ float g_sumsq[COUT];
__device__ float g_scale[COUT];
__device__ float g_shift[COUT];

// ---------------- L1: prep (W = W1@Wc, bias2, zero scratch) ----------------
__global__ __launch_bounds__(256) void prep_kernel(const float* __restrict__ W1,
                                                   const float* __restrict__ b1,
                                                   const float* __restrict__ Wc,
                                                   const float* __restrict__ bc) {
    int bx = blockIdx.x, tid = threadIdx.x;
    if (bx < 64) {
        // one row c = bx of W: dot length 128, coalesced over o=tid
        float acc = 0.f;
        const float* w1 = W1 + bx * CMLP;
#pragma unroll 8
        for (int m = 0; m < CMLP; m++) acc = fmaf(w1[m], Wc[m * COUT + tid], acc);
        g_W[bx * COUT + tid] = acc;
    } else if (bx == 64) {
        float acc = bc[tid];
#pragma unroll 8
        for (int m = 0; m < CMLP; m++) acc = fmaf(b1[m], Wc[m * COUT + tid], acc);
        g_bias2[tid] = acc;
        g_sum[tid] = 0.f;
        g_sumsq[tid] = 0.f;
    } else {
        // blocks 65..80 zero g_cnt (16 blocks * 2048 ints)
        int base = (bx - 65) * 2048 + tid;
#pragma unroll
        for (int i = 0; i < 8; i++) g_cnt[base + i * 256] = 0;
    }
}

// ---------------- L2: fused FPS (blocks 0..7) + feats2 GEMM (blocks 8..) ----
__global__ __launch_bounds__(256) void fps_gemm_kernel(const float* __restrict__ xyz,
                                                       const float* __restrict__ points) {
    __shared__ float As[64][68];            // GEMM A tile (transposed), padded
    __shared__ unsigned swv[2][8];          // FPS per-warp partial values
    __shared__ int      swi[2][8];          // FPS per-warp partial indices
    const int tid = threadIdx.x;

    if (blockIdx.x < B_) {
        // ================= FPS: one CTA per batch =================
        const int b = blockIdx.x;
        const float* X = xyz + (size_t)b * N_ * 3;
        const int lane = tid & 31, w = tid >> 5;
        const int base = tid * 16;   // thread owns points [base, base+16)

        float px[16], py[16], pz[16], dm[16];
#pragma unroll
        for (int i = 0; i < 16; i++) {
            px[i] = X[(base + i) * 3 + 0];
            py[i] = X[(base + i) * 3 + 1];
            pz[i] = X[(base + i) * 3 + 2];
            dm[i] = 1e10f;
        }

        int far = 0;
        if (tid == 0) g_fps[b * S_ + 0] = 0;

        for (int it = 1; it < S_; ++it) {
            const float cx = __ldg(&X[far * 3 + 0]);
            const float cy = __ldg(&X[far * 3 + 1]);
            const float cz = __ldg(&X[far * 3 + 2]);

            float bestv = -1.f; int bestl = 0;
#pragma unroll
            for (int i = 0; i < 16; i++) {
                float dx = px[i] - cx, dy = py[i] - cy, dz = pz[i] - cz;
                float d = fmaf(dz, dz, fmaf(dy, dy, dx * dx));
                float v = fminf(dm[i], d);
                dm[i] = v;
                bool p = v > bestv;        // strict > keeps first (lowest) index
                bestv = p ? v : bestv;
                bestl = p ? i : bestl;
            }
            // warp argmax: positive-float bits are order-preserving as uint
            unsigned ub = __float_as_uint(bestv);
            unsigned m  = __reduce_max_sync(0xffffffffu, ub);
            unsigned bal = __ballot_sync(0xffffffffu, ub == m);
            int wbest = __shfl_sync(0xffffffffu, base + bestl, __ffs(bal) - 1);

            const int pr = it & 1;          // double-buffer -> single barrier/iter
            if (lane == 0) { swv[pr][w] = m; swi[pr][w] = wbest; }
            __syncthreads();

            unsigned v2  = (lane < 8) ? swv[pr][lane] : 0u;
            unsigned m2  = __reduce_max_sync(0xffffffffu, v2);
            unsigned bal2 = __ballot_sync(0xffffffffu, (v2 == m2) && (lane < 8));
            int idx2 = (lane < 8) ? swi[pr][lane] : 0;
            far = __shfl_sync(0xffffffffu, idx2, __ffs(bal2) - 1);

            if (tid == 0) g_fps[b * S_ + it] = far;
        }
    } else {
        // ================= GEMM: feats2 = points @ W + bias2 =================
        // tile: 64 rows x 128 cols, 256 threads, each thread 8x4 outputs
        const int gb = blockIdx.x - B_;
        const int rt = gb & 511;            // 512 row tiles of 64
        const int ct = gb >> 9;             // 2 col tiles of 128

        // cooperative load of A tile (64 rows x 64 k), store transposed
        {
            const int rin = tid >> 4, k4 = tid & 15;
#pragma unroll
            for (int i = 0; i < 4; i++) {
                int r = rin + 16 * i;
                float4 v = *(const float4*)(points + ((size_t)(rt * 64 + r)) * 64 + k4 * 4);
                As[k4 * 4 + 0][r] = v.x;
                As[k4 * 4 + 1][r] = v.y;
                As[k4 * 4 + 2][r] = v.z;
                As[k4 * 4 + 3][r] = v.w;
            }
        }
        __syncthreads();

        const int col0 = ct * 128 + (tid & 31) * 4;
        const int r0   = (tid >> 5) * 8;

        float acc[8][4];
#pragma unroll
        for (int i = 0; i < 8; i++)
#pragma unroll
            for (int j = 0; j < 4; j++) acc[i][j] = 0.f;

#pragma unroll 8
        for (int k = 0; k < 64; k++) {
            float4 b4 = *(const float4*)(g_W + k * COUT + col0);
            float4 a0 = *(const float4*)&As[k][r0];
            float4 a1 = *(const float4*)&As[k][r0 + 4];
            float a[8] = {a0.x, a0.y, a0.z, a0.w, a1.x, a1.y, a1.z, a1.w};
            float bv[4] = {b4.x, b4.y, b4.z, b4.w};
#pragma unroll
            for (int i = 0; i < 8; i++)
#pragma unroll
                for (int j = 0; j < 4; j++)
                    acc[i][j] = fmaf(a[i], bv[j], acc[i][j]);
        }

        float4 bb = *(const float4*)(g_bias2 + col0);
#pragma unroll
        for (int i = 0; i < 8; i++) {
            float4 o;
            o.x = acc[i][0] + bb.x;
            o.y = acc[i][1] + bb.y;
            o.z = acc[i][2] + bb.z;
            o.w = acc[i][3] + bb.w;
            *(float4*)(g_feats2 + ((size_t)(rt * 64 + r0 + i)) * COUT + col0) = o;
        }
    }
}

// ---------------- L3: ball query (one warp per query) ----------------
__global__ __launch_bounds__(256) void ball_kernel(const float* __restrict__ xyz) {
    const int w = threadIdx.x >> 5, lane = threadIdx.x & 31;
    const int q = blockIdx.x * 8 + w;       // 0..8191
    const int b = q >> 10;
    const float* X = xyz + (size_t)b * N_ * 3;
    const int ci = g_fps[q];
    const float cx = X[ci * 3 + 0], cy = X[ci * 3 + 1], cz = X[ci * 3 + 2];

    int cnt = 0, first = -1;
    int* out = g_gidx + q * NS_;

    for (int base = 0; base < N_; base += 32) {
        int p = base + lane;
        float dx = X[p * 3 + 0] - cx;
        float dy = X[p * 3 + 1] - cy;
        float dz = X[p * 3 + 2] - cz;
        float d = fmaf(dz, dz, fmaf(dy, dy, dx * dx));
        bool in = (d <= R2_);
        unsigned bal = __ballot_sync(0xffffffffu, in);
        if (first < 0 && bal) first = base + __ffs(bal) - 1;
        int slot = cnt + __popc(bal & ((1u << lane) - 1));
        if (in && slot < NS_) {
            out[slot] = p;
            atomicAdd(&g_cnt[b * N_ + p], 1);
        }
        cnt += __popc(bal);
        if (cnt >= NS_) break;              // uniform across warp
    }
    if (cnt < NS_) {
        for (int s2 = cnt + lane; s2 < NS_; s2 += 32) out[s2] = first;
        if (lane == 0) atomicAdd(&g_cnt[b * N_ + first], NS_ - cnt);
    }
}

// ---------------- L4: count-weighted BN stats ----------------
__global__ __launch_bounds__(256) void stats_kernel() {
    const int tid = threadIdx.x;
    const int row0 = blockIdx.x * 128;
    float s = 0.f, s2 = 0.f;
#pragma unroll 4
    for (int r = 0; r < 128; r++) {
        int c = g_cnt[row0 + r];            // uniform broadcast load
        if (c) {
            float v = g_feats2[(size_t)(row0 + r) * COUT + tid];
            float cf = (float)c;
            s  += cf * v;
            s2  = fmaf(cf * v, v, s2);
        }
    }
    atomicAdd(&g_sum[tid], s);
    atomicAdd(&g_sumsq[tid], s2);
}

// ---------------- L4b: finalize scale/shift ----------------
__global__ __launch_bounds__(256) void finalize_kernel(const float* __restrict__ gamma,
                                                       const float* __restrict__ beta) {
    const int o = threadIdx.x;
    const float M = (float)(B_ * S_ * NS_);  // 262144
    float mean = g_sum[o] / M;
    float var  = g_sumsq[o] / M - mean * mean;
    float sc = gamma[o] * rsqrtf(var + 1e-5f);
    g_scale[o] = sc;
    g_shift[o] = beta[o] - mean * sc;
}

// ---------------- L5: gather + affine + relu + max ----------------
__global__ __launch_bounds__(256) void out_kernel(float* __restrict__ out) {
    __shared__ int gi[NS_];
    const int q = blockIdx.x;               // b*1024 + s
    const int tid = threadIdx.x;            // channel o
    if (tid < NS_) gi[tid] = g_gidx[q * NS_ + tid];
    __syncthreads();

    const int b = q >> 10;
    const float* F = g_feats2 + (size_t)b * N_ * COUT + tid;
    float mx = -3.4e38f, mn = 3.4e38f;
#pragma unroll
    for (int n = 0; n < NS_; n++) {
        float v = F[(size_t)gi[n] * COUT];  // coalesced: consecutive tid -> consecutive addr
        mx = fmaxf(mx, v);
        mn = fminf(mn, v);
    }
    float sc = g_scale[tid];
    float m = (sc >= 0.f) ? mx : mn;        // affine+relu commutes with max (sign-aware)
    float r = fmaf(sc, m, g_shift[tid]);
    out[(size_t)q * COUT + tid] = fmaxf(r, 0.f);
}

// ---------------- launch ----------------
extern "C" void kernel_launch(void* const* d_in, const int* in_sizes, int n_in,
                              void* d_out, int out_size) {
    const float* xyz    = (const float*)d_in[0];
    // d_in[1] = t, unused by the reference
    const float* points = (const float*)d_in[2];
    const float* W1     = (const float*)d_in[3];
    const float* b1     = (const float*)d_in[4];
    const float* Wc     = (const float*)d_in[5];
    const float* bc     = (const float*)d_in[6];
    const float* gamma  = (const float*)d_in[7];
    const float* beta   = (const float*)d_in[8];
    float* out = (float*)d_out;

    prep_kernel<<<81, 256>>>(W1, b1, Wc, bc);
    fps_gemm_kernel<<<8 + 1024, 256>>>(xyz, points);
    ball_kernel<<<1024, 256>>>(xyz);
    stats_kernel<<<256, 256>>>();
    finalize_kernel<<<1, 256>>>(gamma, beta);
    out_kernel<<<8192, 256>>>(out);
}